// round 6
// baseline (speedup 1.0000x reference)
#include <cuda_runtime.h>
#include <cuda_bf16.h>

// GeometricHyperConnections — fused, HBM-bound.
// b=4, s=4, T=2048, d=2048, k=4.
// One CTA per (b,t) token; 256 threads; ONE block barrier.
// NO SMEM staging: pass-2 re-reads r via LDG (L1/L2-resident), which costs the
// same L1TEX wavefronts as LDS but removes all STS traffic. branch_input is
// accumulated in pass-1 registers (hp known up front) and stored immediately.

#define T_DIM 2048
#define D_DIM 2048
#define D4    512         // D_DIM/4
#define B_DIM 4
#define S_DIM 4
#define K_DIM 4
#define TAU   0.05f
#define LOGM  (-1.3862943611198906f)   // -log(4)
#define RMSEPS 1e-6f

__global__ void __launch_bounds__(256, 4)
ghc_kernel(const float* __restrict__ resid,
           const float* __restrict__ branch,
           const float* __restrict__ rmsw,
           const float* __restrict__ projW,
           const float* __restrict__ log_sigma,
           const float* __restrict__ pre_logits,
           const float* __restrict__ post_logits,
           float* __restrict__ out_bi,     // (B,T,D)
           float* __restrict__ out_mix)    // (B*S,T,D)
{
    __shared__ float red[8][20];           // per-warp partials
    __shared__ float coords_w[8][16];      // per-warp private scratch
    __shared__ float Hs_w[8][16];          // per-warp H result

    const int tid  = threadIdx.x;
    const int warp = tid >> 5, lane = tid & 31;
    const int m    = blockIdx.x;
    const int bi   = m >> 11;              // m / T_DIM
    const int t    = m & (T_DIM - 1);

    const float4* R4  = (const float4*)resid;
    const float4* W4  = (const float4*)rmsw;
    const float4* P4  = (const float4*)projW;
    const float4* BO4 = (const float4*)branch;

    unsigned rbase[S_DIM];
#pragma unroll
    for (int si = 0; si < S_DIM; si++)
        rbase[si] = (unsigned)((bi * S_DIM + si) * T_DIM + t) * D4;
    const unsigned bbase = (unsigned)(bi * T_DIM + t) * D4;

    // ---- Hpre / Hpost: every thread computes both tiny softmaxes ----------
    float hp[4], hq[4];
    {
        float l[4], mx, sm;
#pragma unroll
        for (int i = 0; i < 4; i++) l[i] = __ldg(&pre_logits[i]);
        mx = fmaxf(fmaxf(l[0], l[1]), fmaxf(l[2], l[3]));
        sm = 0.f;
#pragma unroll
        for (int i = 0; i < 4; i++) { hp[i] = __expf(l[i] - mx); sm += hp[i]; }
        sm = 1.f / sm;
#pragma unroll
        for (int i = 0; i < 4; i++) hp[i] *= sm;
#pragma unroll
        for (int i = 0; i < 4; i++) l[i] = __ldg(&post_logits[i]);
        mx = fmaxf(fmaxf(l[0], l[1]), fmaxf(l[2], l[3]));
        sm = 0.f;
#pragma unroll
        for (int i = 0; i < 4; i++) { hq[i] = __expf(l[i] - mx); sm += hq[i]; }
        sm = 1.f / sm;
#pragma unroll
        for (int i = 0; i < 4; i++) hq[i] *= sm;
    }

    float4* OBI = (float4*)out_bi;
    float4* OMX = (float4*)out_mix;

    // ---------------- Pass 1: stats + branch_input, no staging -------------
    // acc[0..3] = sumsq[s]; acc[4 + s*4 + k] = dot[s][k]
    float acc[20];
#pragma unroll
    for (int v = 0; v < 20; v++) acc[v] = 0.f;

#pragma unroll
    for (int j = 0; j < 2; j++) {
        const int c = tid + j * 256;
        const float4 w  = W4[c];
        const float4 p0 = P4[0 * D4 + c];
        const float4 p1 = P4[1 * D4 + c];
        const float4 p2 = P4[2 * D4 + c];
        const float4 p3 = P4[3 * D4 + c];
        float4 o = make_float4(0.f, 0.f, 0.f, 0.f);
#pragma unroll
        for (int s = 0; s < S_DIM; s++) {
            const float4 r = R4[rbase[s] + c];    // default cache: keep in L1/L2
            acc[s] += r.x*r.x + r.y*r.y + r.z*r.z + r.w*r.w;
            const float ax = r.x*w.x, ay = r.y*w.y, az = r.z*w.z, aw = r.w*w.w;
            acc[4 + s*4 + 0] += ax*p0.x + ay*p0.y + az*p0.z + aw*p0.w;
            acc[4 + s*4 + 1] += ax*p1.x + ay*p1.y + az*p1.z + aw*p1.w;
            acc[4 + s*4 + 2] += ax*p2.x + ay*p2.y + az*p2.z + aw*p2.w;
            acc[4 + s*4 + 3] += ax*p3.x + ay*p3.y + az*p3.z + aw*p3.w;
            o.x += hp[s] * r.x;
            o.y += hp[s] * r.y;
            o.z += hp[s] * r.z;
            o.w += hp[s] * r.w;
        }
        __stcs(&OBI[bbase + c], o);               // branch_input done in pass 1
    }

#pragma unroll
    for (int v = 0; v < 20; v++) {
        float x = acc[v];
#pragma unroll
        for (int off = 16; off; off >>= 1)
            x += __shfl_xor_sync(0xffffffffu, x, off);
        acc[v] = x;
    }
    if (lane == 0) {
#pragma unroll
        for (int v = 0; v < 20; v++) red[warp][v] = acc[v];
    }

    __syncthreads();   // the ONLY block barrier

    // ---- Every warp: coords + Sinkhorn (lanes 0-15), fully parallel -------
    if (lane < 16) {
        const int si = lane >> 2;
        float ssq = 0.f, dsum = 0.f;
#pragma unroll
        for (int w = 0; w < 8; w++) {
            ssq  += red[w][si];
            dsum += red[w][4 + lane];
        }
        const float scale = rsqrtf(ssq * (1.f / (float)D_DIM) + RMSEPS);
        coords_w[warp][lane] = scale * dsum;
    }
    __syncwarp();
    if (lane < 16) {
        const int i = lane >> 2, jj = lane & 3;
        float ds = 0.f;
#pragma unroll
        for (int k = 0; k < K_DIM; k++) {
            const float df = coords_w[warp][i * 4 + k] - coords_w[warp][jj * 4 + k];
            ds += df * df;
        }
        const float sigma_sq = __expf(2.f * __ldg(log_sigma));
        const float Z = -ds / (2.f * sigma_sq * TAU);

        float u = 0.f, v = 0.f;
        const unsigned M = 0x0000ffffu;
#pragma unroll
        for (int it = 0; it < 10; it++) {
            float t0 = Z + v;
            float mx = t0;
            mx = fmaxf(mx, __shfl_xor_sync(M, mx, 1));
            mx = fmaxf(mx, __shfl_xor_sync(M, mx, 2));
            float p = __expf(t0 - mx);
            p += __shfl_xor_sync(M, p, 1);
            p += __shfl_xor_sync(M, p, 2);
            u = LOGM - (mx + __logf(p));
            float t1 = Z + u;
            mx = t1;
            mx = fmaxf(mx, __shfl_xor_sync(M, mx, 4));
            mx = fmaxf(mx, __shfl_xor_sync(M, mx, 8));
            p = __expf(t1 - mx);
            p += __shfl_xor_sync(M, p, 4);
            p += __shfl_xor_sync(M, p, 8);
            v = LOGM - (mx + __logf(p));
        }
        Hs_w[warp][lane] = __expf(Z + u + v) * (float)S_DIM;
    }
    __syncwarp();

    // ---------------- Pass 2: mixed outputs (r re-read, L1/L2-hot) ---------
    const float* H = Hs_w[warp];
#pragma unroll
    for (int j = 0; j < 2; j++) {
        const int c = tid + j * 256;
        const float4 r0 = __ldg(&R4[rbase[0] + c]);
        const float4 r1 = __ldg(&R4[rbase[1] + c]);
        const float4 r2 = __ldg(&R4[rbase[2] + c]);
        const float4 r3 = __ldg(&R4[rbase[3] + c]);
        const float4 bo = __ldcs(&BO4[bbase + c]);

#pragma unroll
        for (int u = 0; u < 4; u++) {
            const float h0 = H[0 * 4 + u], h1 = H[1 * 4 + u],
                        h2 = H[2 * 4 + u], h3 = H[3 * 4 + u], hb = hq[u];
            float4 q;
            q.x = hb*bo.x + h0*r0.x + h1*r1.x + h2*r2.x + h3*r3.x;
            q.y = hb*bo.y + h0*r0.y + h1*r1.y + h2*r2.y + h3*r3.y;
            q.z = hb*bo.z + h0*r0.z + h1*r1.z + h2*r2.z + h3*r3.z;
            q.w = hb*bo.w + h0*r0.w + h1*r1.w + h2*r2.w + h3*r3.w;
            __stcs(&OMX[rbase[u] + c], q);
        }
    }
}

extern "C" void kernel_launch(void* const* d_in, const int* in_sizes, int n_in,
                              void* d_out, int out_size)
{
    const float* resid       = (const float*)d_in[0];
    const float* branch      = (const float*)d_in[1];
    const float* rmsw        = (const float*)d_in[2];
    const float* projW       = (const float*)d_in[3];
    const float* log_sigma   = (const float*)d_in[4];
    const float* pre_logits  = (const float*)d_in[5];
    const float* post_logits = (const float*)d_in[6];

    float* out_bi  = (float*)d_out;                                   // (B,T,D) first
    float* out_mix = (float*)d_out + (size_t)B_DIM * T_DIM * D_DIM;   // then (B*S,T,D)

    dim3 grid(B_DIM * T_DIM);
    dim3 block(256);
    ghc_kernel<<<grid, block>>>(resid, branch, rmsw, projW, log_sigma,
                                pre_logits, post_logits, out_bi, out_mix);
}